// round 10
// baseline (speedup 1.0000x reference)
#include <cuda_runtime.h>
#include <math.h>

#define TT 512
#define BB 64
#define II 512
#define HH 512
#define G4 2048
#define NCTA 128
#define CPG 64          // CTAs per group
#define BPG 32          // batches per group
#define HPC 8           // h-cols per CTA
#define NCC 32          // gate-cols per CTA (4 gates x 8 h)
#define PROW 36         // padded partial row (floats)
#define NW 16           // warps per CTA (= k-sections)

typedef unsigned long long ull;

// ---------------- scratch ----------------------------------------------------
// xT2: [T][I][grp][16 lb][2 beta] floats  (batch b = grp*32 + lb + 16*beta)
__device__ float g_xT[(size_t)TT * II * BB];
// slab layout per producer: [8 h][16 lb][2 beta] floats (256 per slab)
__device__ float g_a4[4][2][CPG][BPG * HPC];
__device__ unsigned int g_flagP[NCTA][32];               // 128B-padded flags

// ---------------- f32x2 helpers ----------------------------------------------
#define FMA2(d, a, b, c) \
    asm("fma.rn.f32x2 %0, %1, %2, %3;" : "=l"(d) : "l"(a), "l"(b), "l"(c))

__device__ __forceinline__ ull packf2(float lo, float hi) {
    return (ull)__float_as_uint(lo) | ((ull)__float_as_uint(hi) << 32);
}
__device__ __forceinline__ float sum2(ull v) {
    return __uint_as_float((unsigned)v) + __uint_as_float((unsigned)(v >> 32));
}

__device__ __forceinline__ void st_release_gpu(unsigned int* p, unsigned int v) {
    asm volatile("st.release.gpu.global.u32 [%0], %1;" :: "l"(p), "r"(v) : "memory");
}
__device__ __forceinline__ unsigned int ld_acquire_gpu(const unsigned int* p) {
    unsigned int v;
    asm volatile("ld.acquire.gpu.global.u32 %0, [%1];" : "=r"(v) : "l"(p) : "memory");
    return v;
}
__device__ __forceinline__ void wait_flag(const unsigned int* p, unsigned int target) {
    if ((int)(ld_acquire_gpu(p) - target) >= 0) return;
    while ((int)(ld_acquire_gpu(p) - target) < 0) { __nanosleep(40); }
}

// ---------------- phase 0: transpose x -> [T][I][grp][lb][beta] ---------------
__global__ void __launch_bounds__(256) transpose_x_kernel(const float* __restrict__ X)
{
    __shared__ float tile[32][33];
    const int i0 = blockIdx.x * 32;
    const int b0 = blockIdx.y * 32;   // batch-block = group (32 batches)
    const int t  = blockIdx.z;
    const int tx = threadIdx.x;
    const int ty = threadIdx.y;
    const int grp = b0 >> 5;

#pragma unroll
    for (int r = 0; r < 32; r += 8)
        tile[ty + r][tx] = X[((size_t)t * BB + b0 + ty + r) * II + i0 + tx];
    __syncthreads();
    // write: for row i = i0+ty+r, batch-in-group bg = tx -> slot (bg&15)*2 + (bg>>4)
    const int slot = (tx & 15) * 2 + (tx >> 4);
#pragma unroll
    for (int r = 0; r < 32; r += 8) {
        int i = i0 + ty + r;
        g_xT[(((size_t)t * II + i) * 2 + grp) * 32 + slot] = tile[tx][ty + r];
    }
}

// ---------------- fused persistent recurrence + inline x@W --------------------
__device__ __forceinline__ float sigmoidf_(float x) { return 1.0f / (1.0f + expf(-x)); }

extern __shared__ float dyn_smem[];

// smem: Up [256 kp][8 j][2 lc][2 o] ull (64KB) | Wp same (64KB)
//     | part [16 ks][32 b][PROW] float (72KB)
__global__ void __launch_bounds__(512, 1) rnn_kernel(
    const float* __restrict__ a0,
    const float* __restrict__ U,
    const float* __restrict__ W,
    const float* __restrict__ bias,
    float* __restrict__ out)
{
    ull*   Up   = (ull*)dyn_smem;
    ull*   Wp   = Up + 256 * NCC;
    float* part = (float*)(Wp + 256 * NCC);

    const int tid  = threadIdx.x;
    const int cta  = blockIdx.x;
    const int grp  = cta >> 6;           // 0..1
    const int p    = cta & 63;           // producer index in group
    const int hc0  = p * HPC;
    const int w    = tid >> 5;           // warp = ksec 0..15 (k-range 32)
    const int lane = tid & 31;
    const int lb   = lane & 15;          // batch-group: batches lb, lb+16
    const int lc   = lane >> 4;          // col-half: cols lc*16 .. lc*16+16

    // activation mapping (threads 0..255 only)
    const int bA = (tid >> 3) & 31;      // 0..31 batch in group
    const int hA = tid & 7;              // 0..7
    const int bG = grp * BPG + bA;
    const int hG = hc0 + hA;
    const bool act = (tid < 256);
    const int slotA = hA * 32 + (bA & 15) * 2 + (bA >> 4);  // slab write slot

    // Build paired slices.
    // Flat ull index = ((kp*8 + j)*2 + lc)*2 + o ; col cc = lc*16 + 2*j + o
    for (int idx = tid; idx < 256 * NCC; idx += 512) {
        int o  = idx & 1;
        int lcb = (idx >> 1) & 1;
        int j  = (idx >> 2) & 7;
        int kp = idx >> 5;
        int cc = lcb * 16 + 2 * j + o;
        int gcol = (cc >> 3) * HH + hc0 + (cc & 7);
        Up[idx] = packf2(U[(size_t)(2 * kp) * G4 + gcol],
                         U[(size_t)(2 * kp + 1) * G4 + gcol]);
        Wp[idx] = packf2(W[(size_t)(2 * kp) * G4 + gcol],
                         W[(size_t)(2 * kp + 1) * G4 + gcol]);
    }

    float bias_r[4];
#pragma unroll
    for (int g = 0; g < 4; g++) bias_r[g] = bias[g * HH + hG];

    const unsigned int base = ld_acquire_gpu(&g_flagP[cta][0]);

    // publish a_{-1} = a0 slab into ring slot 3 (new slab layout)
    float aprev = 0.f;
    if (act) {
        aprev = a0[(size_t)bG * HH + hG];
        g_a4[3][grp][p][slotA] = aprev;
    }
    __syncthreads();
    if (tid == 0) st_release_gpu(&g_flagP[cta][0], base + 1);

    for (int t = 0; t < TT; ++t) {
        const int rb = (t + 3) & 3;
        const int wbuf = t & 3;
        const unsigned int target = base + (unsigned)t + 1;

        ull acc0[16], acc1[16];          // [batch lb | lb+16][16 cols]
#pragma unroll
        for (int c = 0; c < 16; c++) { acc0[c] = 0ull; acc1[c] = 0ull; }

        // ---- x-part: warp w covers i in [w*32, w*32+32), 4 blocks of 8 ----
        {
#pragma unroll
            for (int blk = 0; blk < 4; blk++) {
                float2 f[8];
#pragma unroll
                for (int h = 0; h < 8; h++) {
                    int i = w * 32 + blk * 8 + h;
                    f[h] = __ldg((const float2*)&g_xT[(((size_t)t * II + i) * 2 + grp) * 32 + lb * 2]);
                }
#pragma unroll
                for (int q = 0; q < 4; q++) {
                    int kp = w * 16 + blk * 4 + q;
                    ull av0 = packf2(f[2 * q].x, f[2 * q + 1].x);
                    ull av1 = packf2(f[2 * q].y, f[2 * q + 1].y);
                    const ulonglong2* wb = (const ulonglong2*)Wp + kp * 16 + lc;
#pragma unroll
                    for (int j = 0; j < 8; j++) {
                        ulonglong2 uv = wb[j * 2];
                        FMA2(acc0[2 * j],     av0, uv.x, acc0[2 * j]);
                        FMA2(acc0[2 * j + 1], av0, uv.y, acc0[2 * j + 1]);
                        FMA2(acc1[2 * j],     av1, uv.x, acc1[2 * j]);
                        FMA2(acc1[2 * j + 1], av1, uv.y, acc1[2 * j + 1]);
                    }
                }
            }
        }

        // ---- wait for a_{t-1}: warp 0 polls all 64 in-group flags ----
        if (w == 0) {
            wait_flag(&g_flagP[grp * 64 + lane][0], target);
            wait_flag(&g_flagP[grp * 64 + 32 + lane][0], target);
        }
        __syncthreads();

        // ---- a-part: warp w streams slabs [w*4, w*4+4) ----
        {
            const float* abase = &g_a4[rb][grp][0][0];
#pragma unroll
            for (int s = 0; s < 4; s++) {
                int ps = w * 4 + s;
                const float2* sp = (const float2*)(abase + ps * 256) + lb;
                float2 f[8];
#pragma unroll
                for (int h = 0; h < 8; h++)
                    f[h] = __ldcg(&sp[h * 16]);
#pragma unroll
                for (int q = 0; q < 4; q++) {
                    int kp = ps * 4 + q;
                    ull av0 = packf2(f[2 * q].x, f[2 * q + 1].x);
                    ull av1 = packf2(f[2 * q].y, f[2 * q + 1].y);
                    const ulonglong2* ub = (const ulonglong2*)Up + kp * 16 + lc;
#pragma unroll
                    for (int j = 0; j < 8; j++) {
                        ulonglong2 uv = ub[j * 2];
                        FMA2(acc0[2 * j],     av0, uv.x, acc0[2 * j]);
                        FMA2(acc0[2 * j + 1], av0, uv.y, acc0[2 * j + 1]);
                        FMA2(acc1[2 * j],     av1, uv.x, acc1[2 * j]);
                        FMA2(acc1[2 * j + 1], av1, uv.y, acc1[2 * j + 1]);
                    }
                }
            }
        }

        // ---- store partials: rows (w*32 + lb) and (w*32 + lb + 16) ----
        {
            float* pr0 = &part[(w * 32 + lb) * PROW + lc * 16];
            float* pr1 = &part[(w * 32 + lb + 16) * PROW + lc * 16];
#pragma unroll
            for (int m = 0; m < 4; m++) {
                float4 v0, v1;
                v0.x = sum2(acc0[4 * m + 0]); v0.y = sum2(acc0[4 * m + 1]);
                v0.z = sum2(acc0[4 * m + 2]); v0.w = sum2(acc0[4 * m + 3]);
                v1.x = sum2(acc1[4 * m + 0]); v1.y = sum2(acc1[4 * m + 1]);
                v1.z = sum2(acc1[4 * m + 2]); v1.w = sum2(acc1[4 * m + 3]);
                *(float4*)&pr0[4 * m] = v0;
                *(float4*)&pr1[4 * m] = v1;
            }
        }
        __syncthreads();

        // ---- reduce over 16 ksec + bias + activations (threads 0..255) ----
        float a_t = 0.f;
        if (act) {
            float gsum[4];
#pragma unroll
            for (int g = 0; g < 4; g++) {
                int cc = g * 8 + hA;
                float s = bias_r[g];
#pragma unroll
                for (int ks = 0; ks < NW; ks++)
                    s += part[(ks * 32 + bA) * PROW + cc];
                gsum[g] = s;
            }

            float gu   = sigmoidf_(gsum[0]);
            float gf   = sigmoidf_(gsum[1]);
            float go   = sigmoidf_(gsum[2]);
            float cand = tanhf(gsum[3]);
            float c_t  = gu * cand + gf * aprev;
            a_t = go * tanhf(c_t);
            aprev = a_t;

            g_a4[wbuf][grp][p][slotA] = a_t;
        }
        __syncthreads();
        if (tid == 0) st_release_gpu(&g_flagP[cta][0], base + (unsigned)t + 2);

        if (act) out[((size_t)t * BB + bG) * HH + hG] = a_t;
    }
}

// ---------------- launch ------------------------------------------------------
extern "C" void kernel_launch(void* const* d_in, const int* in_sizes, int n_in,
                              void* d_out, int out_size)
{
    const float* x  = (const float*)d_in[0];
    const float* a0 = (const float*)d_in[1];
    const float* W  = (const float*)d_in[2];
    const float* U  = (const float*)d_in[3];
    const float* bb = (const float*)d_in[4];
    float* out = (float*)d_out;

    dim3 gT(II / 32, BB / 32, TT);
    transpose_x_kernel<<<gT, dim3(32, 8)>>>(x);

    const int smem_bytes = 256 * NCC * 8 * 2        // Up + Wp (128KB)
                         + NW * 32 * PROW * 4;      // partials (72KB)
    cudaFuncSetAttribute(rnn_kernel, cudaFuncAttributeMaxDynamicSharedMemorySize, smem_bytes);
    rnn_kernel<<<NCTA, 512, smem_bytes>>>(a0, U, W, bb, out);
}

// round 13
// speedup vs baseline: 1.3926x; 1.3926x over previous
#include <cuda_runtime.h>
#include <math.h>

#define TT 512
#define BB 64
#define II 512
#define HH 512
#define G4 2048
#define NCTA 128
#define CPG 64          // CTAs per group
#define BPG 32          // batches per group
#define HPC 8           // h-cols per CTA
#define NCC 32          // gate-cols per CTA (4 gates x 8 h)
#define PROW 36         // padded partial row (floats)
#define NW 16           // warps per CTA (= k-sections)

typedef unsigned long long ull;

// ---------------- scratch ----------------------------------------------------
// xT: [T][256 kp][2 grp][32 b][2 o] floats; o = i parity  (pre-packed k-pairs)
__device__ float g_xT[(size_t)TT * II * BB];
// slab per producer: [4 kp][32 b][2 o] floats; o = h parity (pre-packed k-pairs)
__device__ float g_a4[4][2][CPG][BPG * HPC];
__device__ unsigned int g_flagP[NCTA][32];               // 128B-padded flags

// ---------------- f32x2 helpers ----------------------------------------------
#define FMA2(d, a, b, c) \
    asm("fma.rn.f32x2 %0, %1, %2, %3;" : "=l"(d) : "l"(a), "l"(b), "l"(c))

__device__ __forceinline__ ull packf2(float lo, float hi) {
    return (ull)__float_as_uint(lo) | ((ull)__float_as_uint(hi) << 32);
}
__device__ __forceinline__ float sum2(ull v) {
    return __uint_as_float((unsigned)v) + __uint_as_float((unsigned)(v >> 32));
}

__device__ __forceinline__ void st_release_gpu(unsigned int* p, unsigned int v) {
    asm volatile("st.release.gpu.global.u32 [%0], %1;" :: "l"(p), "r"(v) : "memory");
}
__device__ __forceinline__ unsigned int ld_acquire_gpu(const unsigned int* p) {
    unsigned int v;
    asm volatile("ld.acquire.gpu.global.u32 %0, [%1];" : "=r"(v) : "l"(p) : "memory");
    return v;
}
__device__ __forceinline__ void wait_flag(const unsigned int* p, unsigned int target) {
    if ((int)(ld_acquire_gpu(p) - target) >= 0) return;
    while ((int)(ld_acquire_gpu(p) - target) < 0) { __nanosleep(40); }
}
__device__ __forceinline__ ull ldg_u64(const ull* p) {
    ull v; asm volatile("ld.global.nc.b64 %0, [%1];" : "=l"(v) : "l"(p)); return v;
}
__device__ __forceinline__ ull ldcg_u64(const ull* p) {
    ull v; asm volatile("ld.global.cg.b64 %0, [%1];" : "=l"(v) : "l"(p)); return v;
}

// ---------------- phase 0: transpose x -> [T][kp][grp][b][o] ------------------
__global__ void __launch_bounds__(256) transpose_x_kernel(const float* __restrict__ X)
{
    __shared__ float tile[32][33];
    const int i0 = blockIdx.x * 32;
    const int b0 = blockIdx.y * 32;
    const int t  = blockIdx.z;
    const int tx = threadIdx.x;
    const int ty = threadIdx.y;
    const int grp = b0 >> 5;

#pragma unroll
    for (int r = 0; r < 32; r += 8)
        tile[ty + r][tx] = X[((size_t)t * BB + b0 + ty + r) * II + i0 + tx];
    __syncthreads();
    // write: for i = i0+ty+r, bg = tx -> xT[(t*256 + (i>>1))*2+grp][bg][i&1]
#pragma unroll
    for (int r = 0; r < 32; r += 8) {
        int i = i0 + ty + r;
        g_xT[(((size_t)t * 256 + (i >> 1)) * 2 + grp) * 64 + tx * 2 + (i & 1)]
            = tile[tx][ty + r];
    }
}

// ---------------- fused persistent recurrence + inline x@W --------------------
__device__ __forceinline__ float sigmoidf_(float x) { return 1.0f / (1.0f + expf(-x)); }

extern __shared__ float dyn_smem[];

// smem: Up [256 kp][8 j][2 lc][2 o] ull (64KB) | Wp same (64KB)
//     | part [16 ks][32 b][PROW] float (72KB)
__global__ void __launch_bounds__(512, 1) rnn_kernel(
    const float* __restrict__ a0,
    const float* __restrict__ U,
    const float* __restrict__ W,
    const float* __restrict__ bias,
    float* __restrict__ out)
{
    ull*   Up   = (ull*)dyn_smem;
    ull*   Wp   = Up + 256 * NCC;
    float* part = (float*)(Wp + 256 * NCC);

    const int tid  = threadIdx.x;
    const int cta  = blockIdx.x;
    const int grp  = cta >> 6;           // 0..1
    const int p    = cta & 63;           // producer index in group
    const int hc0  = p * HPC;
    const int w    = tid >> 5;           // warp = ksec 0..15 (k-range 32)
    const int lane = tid & 31;
    const int lb   = lane & 15;          // batch-group: batches lb, lb+16
    const int lc   = lane >> 4;          // col-half: cols lc*16 .. lc*16+16

    // activation mapping (threads 0..255 only)
    const int bA = (tid >> 3) & 31;      // 0..31 batch in group
    const int hA = tid & 7;              // 0..7
    const int bG = grp * BPG + bA;
    const int hG = hc0 + hA;
    const bool act = (tid < 256);
    const int slotA = (hA >> 1) * 64 + bA * 2 + (hA & 1);   // slab write slot

    // Paired U/W slices: flat ull idx = ((kp*8 + j)*2 + lc)*2 + o, cc = lc*16+2j+o
    for (int idx = tid; idx < 256 * NCC; idx += 512) {
        int o   = idx & 1;
        int lcb = (idx >> 1) & 1;
        int j   = (idx >> 2) & 7;
        int kp  = idx >> 5;
        int cc  = lcb * 16 + 2 * j + o;
        int gcol = (cc >> 3) * HH + hc0 + (cc & 7);
        Up[idx] = packf2(U[(size_t)(2 * kp) * G4 + gcol],
                         U[(size_t)(2 * kp + 1) * G4 + gcol]);
        Wp[idx] = packf2(W[(size_t)(2 * kp) * G4 + gcol],
                         W[(size_t)(2 * kp + 1) * G4 + gcol]);
    }

    float bias_r[4];
#pragma unroll
    for (int g = 0; g < 4; g++) bias_r[g] = bias[g * HH + hG];

    const unsigned int base = ld_acquire_gpu(&g_flagP[cta][0]);

    // publish a_{-1} = a0 slab into ring slot 3 (pre-packed slab layout)
    float aprev = 0.f;
    if (act) {
        aprev = a0[(size_t)bG * HH + hG];
        g_a4[3][grp][p][slotA] = aprev;
    }
    __syncthreads();
    if (tid == 0) st_release_gpu(&g_flagP[cta][0], base + 1);

    for (int t = 0; t < TT; ++t) {
        const int rb = (t + 3) & 3;
        const int wbuf = t & 3;
        const unsigned int target = base + (unsigned)t + 1;

        ull acc0[16], acc1[16];          // [batch lb | lb+16][16 cols]
#pragma unroll
        for (int c = 0; c < 16; c++) { acc0[c] = 0ull; acc1[c] = 0ull; }

        // ---- x-part: warp w covers kp in [w*16, w*16+16), 4 blocks of 4 ----
        {
            const ull* xw = (const ull*)g_xT;
#pragma unroll
            for (int blk = 0; blk < 4; blk++) {
                ull f0[4], f1[4];
#pragma unroll
                for (int q = 0; q < 4; q++) {
                    size_t kp = (size_t)w * 16 + blk * 4 + q;
                    const ull* xp = xw + (((size_t)t * 256 + kp) * 2 + grp) * 32 + lb;
                    f0[q] = ldg_u64(xp);
                    f1[q] = ldg_u64(xp + 16);
                }
#pragma unroll
                for (int q = 0; q < 4; q++) {
                    int kp = w * 16 + blk * 4 + q;
                    const ulonglong2* wb = (const ulonglong2*)Wp + kp * 16 + lc;
#pragma unroll
                    for (int j = 0; j < 8; j++) {
                        ulonglong2 uv = wb[j * 2];
                        FMA2(acc0[2 * j],     f0[q], uv.x, acc0[2 * j]);
                        FMA2(acc0[2 * j + 1], f0[q], uv.y, acc0[2 * j + 1]);
                        FMA2(acc1[2 * j],     f1[q], uv.x, acc1[2 * j]);
                        FMA2(acc1[2 * j + 1], f1[q], uv.y, acc1[2 * j + 1]);
                    }
                }
            }
        }

        // ---- wait for a_{t-1}: warp 0 polls all 64 in-group flags ----
        if (w == 0) {
            wait_flag(&g_flagP[grp * 64 + lane][0], target);
            wait_flag(&g_flagP[grp * 64 + 32 + lane][0], target);
        }
        __syncthreads();

        // ---- a-part: warp w streams slabs [w*4, w*4+4), 4 kp each ----
        {
            const float* abase = &g_a4[rb][grp][0][0];
#pragma unroll
            for (int s = 0; s < 4; s++) {
                int ps = w * 4 + s;
                const ull* sp = (const ull*)(abase + ps * 256);
                ull f0[4], f1[4];
#pragma unroll
                for (int q = 0; q < 4; q++) {
                    f0[q] = ldcg_u64(sp + q * 32 + lb);
                    f1[q] = ldcg_u64(sp + q * 32 + lb + 16);
                }
#pragma unroll
                for (int q = 0; q < 4; q++) {
                    int kp = ps * 4 + q;
                    const ulonglong2* ub = (const ulonglong2*)Up + kp * 16 + lc;
#pragma unroll
                    for (int j = 0; j < 8; j++) {
                        ulonglong2 uv = ub[j * 2];
                        FMA2(acc0[2 * j],     f0[q], uv.x, acc0[2 * j]);
                        FMA2(acc0[2 * j + 1], f0[q], uv.y, acc0[2 * j + 1]);
                        FMA2(acc1[2 * j],     f1[q], uv.x, acc1[2 * j]);
                        FMA2(acc1[2 * j + 1], f1[q], uv.y, acc1[2 * j + 1]);
                    }
                }
            }
        }

        // ---- store partials: rows (w*32 + lb) and (w*32 + lb + 16) ----
        {
            float* pr0 = &part[(w * 32 + lb) * PROW + lc * 16];
            float* pr1 = &part[(w * 32 + lb + 16) * PROW + lc * 16];
#pragma unroll
            for (int m = 0; m < 4; m++) {
                float4 v0, v1;
                v0.x = sum2(acc0[4 * m + 0]); v0.y = sum2(acc0[4 * m + 1]);
                v0.z = sum2(acc0[4 * m + 2]); v0.w = sum2(acc0[4 * m + 3]);
                v1.x = sum2(acc1[4 * m + 0]); v1.y = sum2(acc1[4 * m + 1]);
                v1.z = sum2(acc1[4 * m + 2]); v1.w = sum2(acc1[4 * m + 3]);
                *(float4*)&pr0[4 * m] = v0;
                *(float4*)&pr1[4 * m] = v1;
            }
        }
        __syncthreads();

        // ---- reduce over 16 ksec + bias + activations (threads 0..255) ----
        float a_t = 0.f;
        if (act) {
            float gsum[4];
#pragma unroll
            for (int g = 0; g < 4; g++) {
                int cc = g * 8 + hA;
                float s = bias_r[g];
#pragma unroll
                for (int ks = 0; ks < NW; ks++)
                    s += part[(ks * 32 + bA) * PROW + cc];
                gsum[g] = s;
            }

            float gu   = sigmoidf_(gsum[0]);
            float gf   = sigmoidf_(gsum[1]);
            float go   = sigmoidf_(gsum[2]);
            float cand = tanhf(gsum[3]);
            float c_t  = gu * cand + gf * aprev;
            a_t = go * tanhf(c_t);
            aprev = a_t;

            g_a4[wbuf][grp][p][slotA] = a_t;
        }
        __syncthreads();
        if (tid == 0) st_release_gpu(&g_flagP[cta][0], base + (unsigned)t + 2);

        if (act) out[((size_t)t * BB + bG) * HH + hG] = a_t;
    }
}

// ---------------- launch ------------------------------------------------------
extern "C" void kernel_launch(void* const* d_in, const int* in_sizes, int n_in,
                              void* d_out, int out_size)
{
    const float* x  = (const float*)d_in[0];
    const float* a0 = (const float*)d_in[1];
    const float* W  = (const float*)d_in[2];
    const float* U  = (const float*)d_in[3];
    const float* bb = (const float*)d_in[4];
    float* out = (float*)d_out;

    dim3 gT(II / 32, BB / 32, TT);
    transpose_x_kernel<<<gT, dim3(32, 8)>>>(x);

    const int smem_bytes = 256 * NCC * 8 * 2        // Up + Wp (128KB)
                         + NW * 32 * PROW * 4;      // partials (72KB)
    cudaFuncSetAttribute(rnn_kernel, cudaFuncAttributeMaxDynamicSharedMemorySize, smem_bytes);
    rnn_kernel<<<NCTA, 512, smem_bytes>>>(a0, U, W, bb, out);
}

// round 15
// speedup vs baseline: 1.4879x; 1.0684x over previous
#include <cuda_runtime.h>
#include <math.h>

#define TT 512
#define BB 64
#define II 512
#define HH 512
#define G4 2048
#define NCTA 128
#define CPG 64          // CTAs per group
#define BPG 32          // batches per group
#define HPC 8           // h-cols per CTA
#define NCC 32          // gate-cols per CTA (4 gates x 8 h)
#define PROW 40         // padded partial row (floats): 40*b mod 32 = 8b -> conflict-free
#define NW 16           // warps per CTA (= k-sections)

typedef unsigned long long ull;

// ---------------- scratch ----------------------------------------------------
// xT: [T][256 kp][2 grp][32 b][2 o] floats; o = i parity  (pre-packed k-pairs)
__device__ float g_xT[(size_t)TT * II * BB];
// slab per producer: [4 kp][32 b][2 o] floats; o = h parity (pre-packed k-pairs)
__device__ float g_a4[4][2][CPG][BPG * HPC];
__device__ unsigned int g_flagP[NCTA][32];               // 128B-padded flags

// ---------------- f32x2 helpers ----------------------------------------------
#define FMA2(d, a, b, c) \
    asm("fma.rn.f32x2 %0, %1, %2, %3;" : "=l"(d) : "l"(a), "l"(b), "l"(c))

__device__ __forceinline__ ull packf2(float lo, float hi) {
    return (ull)__float_as_uint(lo) | ((ull)__float_as_uint(hi) << 32);
}
__device__ __forceinline__ float sum2(ull v) {
    return __uint_as_float((unsigned)v) + __uint_as_float((unsigned)(v >> 32));
}

__device__ __forceinline__ void st_release_gpu(unsigned int* p, unsigned int v) {
    asm volatile("st.release.gpu.global.u32 [%0], %1;" :: "l"(p), "r"(v) : "memory");
}
__device__ __forceinline__ unsigned int ld_acquire_gpu(const unsigned int* p) {
    unsigned int v;
    asm volatile("ld.acquire.gpu.global.u32 %0, [%1];" : "=r"(v) : "l"(p) : "memory");
    return v;
}
__device__ __forceinline__ void wait_flag(const unsigned int* p, unsigned int target) {
    if ((int)(ld_acquire_gpu(p) - target) >= 0) return;
    while ((int)(ld_acquire_gpu(p) - target) < 0) { __nanosleep(40); }
}
__device__ __forceinline__ ull ldg_u64(const ull* p) {
    ull v; asm volatile("ld.global.nc.b64 %0, [%1];" : "=l"(v) : "l"(p)); return v;
}
__device__ __forceinline__ ull ldcg_u64(const ull* p) {
    ull v; asm volatile("ld.global.cg.b64 %0, [%1];" : "=l"(v) : "l"(p)); return v;
}

// ---------------- phase 0: transpose x -> [T][kp][grp][b][o] ------------------
__global__ void __launch_bounds__(256) transpose_x_kernel(const float* __restrict__ X)
{
    __shared__ float tile[32][33];
    const int i0 = blockIdx.x * 32;
    const int b0 = blockIdx.y * 32;
    const int t  = blockIdx.z;
    const int tx = threadIdx.x;
    const int ty = threadIdx.y;
    const int grp = b0 >> 5;

#pragma unroll
    for (int r = 0; r < 32; r += 8)
        tile[ty + r][tx] = X[((size_t)t * BB + b0 + ty + r) * II + i0 + tx];
    __syncthreads();
#pragma unroll
    for (int r = 0; r < 32; r += 8) {
        int i = i0 + ty + r;
        g_xT[(((size_t)t * 256 + (i >> 1)) * 2 + grp) * 64 + tx * 2 + (i & 1)]
            = tile[tx][ty + r];
    }
}

// ---------------- fused persistent recurrence + inline x@W --------------------
__device__ __forceinline__ float sigmoidf_(float x) { return 1.0f / (1.0f + expf(-x)); }

extern __shared__ float dyn_smem[];

// smem: Up [256 kp][8 j][2 lc][2 o] ull (64KB) | Wp same (64KB)
//     | part [16 ks][32 b][PROW] float (80KB)
__global__ void __launch_bounds__(512, 1) rnn_kernel(
    const float* __restrict__ a0,
    const float* __restrict__ U,
    const float* __restrict__ W,
    const float* __restrict__ bias,
    float* __restrict__ out)
{
    ull*   Up   = (ull*)dyn_smem;
    ull*   Wp   = Up + 256 * NCC;
    float* part = (float*)(Wp + 256 * NCC);

    const int tid  = threadIdx.x;
    const int cta  = blockIdx.x;
    const int grp  = cta >> 6;           // 0..1
    const int p    = cta & 63;           // producer index in group
    const int hc0  = p * HPC;
    const int w    = tid >> 5;           // warp = ksec 0..15 (k-range 32)
    const int lane = tid & 31;
    const int lb   = lane & 15;          // batch-group: batches lb, lb+16
    const int lc   = lane >> 4;          // col-half: cols lc*16 .. lc*16+16

    // activation mapping (threads 0..255 only)
    const int bA = (tid >> 3) & 31;      // 0..31 batch in group
    const int hA = tid & 7;              // 0..7
    const int bG = grp * BPG + bA;
    const int hG = hc0 + hA;
    const bool act = (tid < 256);
    const int slotA = (hA >> 1) * 64 + bA * 2 + (hA & 1);   // slab write slot

    // Paired U/W slices: flat ull idx = ((kp*8 + j)*2 + lc)*2 + o, cc = lc*16+2j+o
    for (int idx = tid; idx < 256 * NCC; idx += 512) {
        int o   = idx & 1;
        int lcb = (idx >> 1) & 1;
        int j   = (idx >> 2) & 7;
        int kp  = idx >> 5;
        int cc  = lcb * 16 + 2 * j + o;
        int gcol = (cc >> 3) * HH + hc0 + (cc & 7);
        Up[idx] = packf2(U[(size_t)(2 * kp) * G4 + gcol],
                         U[(size_t)(2 * kp + 1) * G4 + gcol]);
        Wp[idx] = packf2(W[(size_t)(2 * kp) * G4 + gcol],
                         W[(size_t)(2 * kp + 1) * G4 + gcol]);
    }

    float bias_r[4];
#pragma unroll
    for (int g = 0; g < 4; g++) bias_r[g] = bias[g * HH + hG];

    const unsigned int base = ld_acquire_gpu(&g_flagP[cta][0]);

    // publish a_{-1} = a0 slab into ring slot 3 (pre-packed slab layout)
    float aprev = 0.f;
    if (act) {
        aprev = a0[(size_t)bG * HH + hG];
        g_a4[3][grp][p][slotA] = aprev;
    }
    __syncthreads();
    if (tid == 0) st_release_gpu(&g_flagP[cta][0], base + 1);

    // this warp's 4 producers (for per-warp waiting)
    const unsigned int* myflag = (lane < 4)
        ? &g_flagP[grp * 64 + w * 4 + lane][0] : &g_flagP[grp * 64][0];

    for (int t = 0; t < TT; ++t) {
        const int rb = (t + 3) & 3;
        const int wbuf = t & 3;
        const unsigned int target = base + (unsigned)t + 1;

        ull acc0[16], acc1[16];          // [batch lb | lb+16][16 cols]
#pragma unroll
        for (int c = 0; c < 16; c++) { acc0[c] = 0ull; acc1[c] = 0ull; }

        // ---- x-part: warp w covers kp in [w*16, w*16+16), 4 blocks of 4 ----
        {
            const ull* xw = (const ull*)g_xT;
#pragma unroll
            for (int blk = 0; blk < 4; blk++) {
                ull f0[4], f1[4];
#pragma unroll
                for (int q = 0; q < 4; q++) {
                    size_t kp = (size_t)w * 16 + blk * 4 + q;
                    const ull* xp = xw + (((size_t)t * 256 + kp) * 2 + grp) * 32 + lb;
                    f0[q] = ldg_u64(xp);
                    f1[q] = ldg_u64(xp + 16);
                }
#pragma unroll
                for (int q = 0; q < 4; q++) {
                    int kp = w * 16 + blk * 4 + q;
                    const ulonglong2* wb = (const ulonglong2*)Wp + kp * 16 + lc;
#pragma unroll
                    for (int j = 0; j < 8; j++) {
                        ulonglong2 uv = wb[j * 2];
                        FMA2(acc0[2 * j],     f0[q], uv.x, acc0[2 * j]);
                        FMA2(acc0[2 * j + 1], f0[q], uv.y, acc0[2 * j + 1]);
                        FMA2(acc1[2 * j],     f1[q], uv.x, acc1[2 * j]);
                        FMA2(acc1[2 * j + 1], f1[q], uv.y, acc1[2 * j + 1]);
                    }
                }
            }
        }

        // ---- per-warp wait: warp w polls ONLY its 4 producers ----
        if (lane < 4) wait_flag(myflag, target);
        __syncwarp();

        // ---- a-part: warp w streams slabs [w*4, w*4+4), 4 kp each ----
        {
            const float* abase = &g_a4[rb][grp][0][0];
#pragma unroll
            for (int s = 0; s < 4; s++) {
                int ps = w * 4 + s;
                const ull* sp = (const ull*)(abase + ps * 256);
                ull f0[4], f1[4];
#pragma unroll
                for (int q = 0; q < 4; q++) {
                    f0[q] = ldcg_u64(sp + q * 32 + lb);
                    f1[q] = ldcg_u64(sp + q * 32 + lb + 16);
                }
#pragma unroll
                for (int q = 0; q < 4; q++) {
                    int kp = ps * 4 + q;
                    const ulonglong2* ub = (const ulonglong2*)Up + kp * 16 + lc;
#pragma unroll
                    for (int j = 0; j < 8; j++) {
                        ulonglong2 uv = ub[j * 2];
                        FMA2(acc0[2 * j],     f0[q], uv.x, acc0[2 * j]);
                        FMA2(acc0[2 * j + 1], f0[q], uv.y, acc0[2 * j + 1]);
                        FMA2(acc1[2 * j],     f1[q], uv.x, acc1[2 * j]);
                        FMA2(acc1[2 * j + 1], f1[q], uv.y, acc1[2 * j + 1]);
                    }
                }
            }
        }

        // ---- store partials: rows (w*32 + lb) and (w*32 + lb + 16) ----
        {
            float* pr0 = &part[(w * 32 + lb) * PROW + lc * 16];
            float* pr1 = &part[(w * 32 + lb + 16) * PROW + lc * 16];
#pragma unroll
            for (int m = 0; m < 4; m++) {
                float4 v0, v1;
                v0.x = sum2(acc0[4 * m + 0]); v0.y = sum2(acc0[4 * m + 1]);
                v0.z = sum2(acc0[4 * m + 2]); v0.w = sum2(acc0[4 * m + 3]);
                v1.x = sum2(acc1[4 * m + 0]); v1.y = sum2(acc1[4 * m + 1]);
                v1.z = sum2(acc1[4 * m + 2]); v1.w = sum2(acc1[4 * m + 3]);
                *(float4*)&pr0[4 * m] = v0;
                *(float4*)&pr1[4 * m] = v1;
            }
        }
        __syncthreads();

        // ---- reduce over 16 ksec + bias + activations (threads 0..255) ----
        float a_t = 0.f;
        if (act) {
            float gsum[4];
#pragma unroll
            for (int g = 0; g < 4; g++) {
                int cc = g * 8 + hA;
                float s = bias_r[g];
#pragma unroll
                for (int ks = 0; ks < NW; ks++)
                    s += part[(ks * 32 + bA) * PROW + cc];
                gsum[g] = s;
            }

            float gu   = sigmoidf_(gsum[0]);
            float gf   = sigmoidf_(gsum[1]);
            float go   = sigmoidf_(gsum[2]);
            float cand = tanhf(gsum[3]);
            float c_t  = gu * cand + gf * aprev;
            a_t = go * tanhf(c_t);
            aprev = a_t;

            g_a4[wbuf][grp][p][slotA] = a_t;
        }
        __syncthreads();
        if (tid == 0) st_release_gpu(&g_flagP[cta][0], base + (unsigned)t + 2);

        if (act) out[((size_t)t * BB + bG) * HH + hG] = a_t;
    }
}

// ---------------- launch ------------------------------------------------------
extern "C" void kernel_launch(void* const* d_in, const int* in_sizes, int n_in,
                              void* d_out, int out_size)
{
    const float* x  = (const float*)d_in[0];
    const float* a0 = (const float*)d_in[1];
    const float* W  = (const float*)d_in[2];
    const float* U  = (const float*)d_in[3];
    const float* bb = (const float*)d_in[4];
    float* out = (float*)d_out;

    dim3 gT(II / 32, BB / 32, TT);
    transpose_x_kernel<<<gT, dim3(32, 8)>>>(x);

    const int smem_bytes = 256 * NCC * 8 * 2        // Up + Wp (128KB)
                         + NW * 32 * PROW * 4;      // partials (80KB)
    cudaFuncSetAttribute(rnn_kernel, cudaFuncAttributeMaxDynamicSharedMemorySize, smem_bytes);
    rnn_kernel<<<NCTA, 512, smem_bytes>>>(a0, U, W, bb, out);
}